// round 6
// baseline (speedup 1.0000x reference)
#include <cuda_runtime.h>
#include <cuda_fp16.h>
#include <cstddef>

#define EPSF 1e-6f
#define LAMBDAF 0.01f

// Problem constants (fixed shapes)
//  x: (4,16,16,16,16)  a: (4,16,16,16,1)  w: (144,32,4,4)
//  out: p_out (4,14,14,32,16) ++ a_out (4,14,14,32,1)
#define NCAP 144
#define CCAP 32
#define NPOS 784           // 4*14*14
#define POUT_ELEMS 401408  // 784*32*16
#define WHALF_ELEMS (NCAP * CCAP * 16)  // 73728 halves = 144KB (~L1-resident)

typedef unsigned long long u64;

// ---- packed f32x2 helpers (sm_103a; FFMA2 only reachable via PTX) ----
__device__ __forceinline__ u64 pk2(float lo, float hi) {
    u64 r; asm("mov.b64 %0, {%1, %2};" : "=l"(r) : "f"(lo), "f"(hi)); return r;
}
__device__ __forceinline__ float2 upk2(u64 v) {
    float2 r; asm("mov.b64 {%0, %1}, %2;" : "=f"(r.x), "=f"(r.y) : "l"(v)); return r;
}
__device__ __forceinline__ u64 fma2_(u64 a, u64 b, u64 c) {
    u64 d; asm("fma.rn.f32x2 %0, %1, %2, %3;" : "=l"(d) : "l"(a), "l"(b), "l"(c)); return d;
}
__device__ __forceinline__ u64 mul2_(u64 a, u64 b) {
    u64 d; asm("mul.rn.f32x2 %0, %1, %2;" : "=l"(d) : "l"(a), "l"(b)); return d;
}
__device__ __forceinline__ u64 add2_(u64 a, u64 b) {
    u64 d; asm("add.rn.f32x2 %0, %1, %2;" : "=l"(d) : "l"(a), "l"(b)); return d;
}
__device__ __forceinline__ u64 h2f2(__half2 h) {
    float2 f = __half22float2(h); return pk2(f.x, f.y);
}

// fp16 weight staging buffer, layout [n][k2][c][8]:
//   wh[((n*2+k2)*32 + c)*8 + j] = w[n][c][ k2*8 + j ]
__device__ __half g_wh[WHALF_ELEMS];

// One thread produces one uint4 (8 halves) from two float4 loads.
__global__ void convert_w_kernel(const float* __restrict__ w) {
    int q = blockIdx.x * 256 + threadIdx.x;  // 0..9215
    if (q >= WHALF_ELEMS / 8) return;
    int c = q & 31;
    int k2 = (q >> 5) & 1;
    int n = q >> 6;
    const float4* src = reinterpret_cast<const float4*>(w + ((n * 32 + c) << 4) + k2 * 8);
    float4 f0 = __ldg(src + 0), f1 = __ldg(src + 1);
    __half2 h[4];
    h[0] = __floats2half2_rn(f0.x, f0.y);
    h[1] = __floats2half2_rn(f0.z, f0.w);
    h[2] = __floats2half2_rn(f1.x, f1.y);
    h[3] = __floats2half2_rn(f1.z, f1.w);
    reinterpret_cast<uint4*>(g_wh)[q] = *reinterpret_cast<uint4*>(h);
}

__device__ __forceinline__ float warp_max(float v) {
#pragma unroll
    for (int o = 16; o; o >>= 1) v = fmaxf(v, __shfl_xor_sync(0xffffffffu, v, o));
    return v;
}
__device__ __forceinline__ float warp_sum(float v) {
#pragma unroll
    for (int o = 16; o; o >>= 1) v += __shfl_xor_sync(0xffffffffu, v, o);
    return v;
}

struct Smem {
    float pose2[4608];  // [n*32 + p*2 + {0,1}] pose patch, each value DUPLICATED (f32x2-ready)
    float a[144];       // a_in per n
    float WS[8 * 548];  // per-warp reduction staging (stride-17 padded); [0..544) reused as halflog buf
    float S1[544];      // sum r*v   [c*17+p]
    float S2[544];      // sum r*v^2 [c*17+p]
    float MU[544];      // mu        [c*17+p]
    float I2S[544];     // 1/(2 sigma^2)
    float RSB[8 * 33];  // per-warp rsum staging
    float RS[32];       // r_sum per c
    float Lc[32];       // log(a_out+eps) - sum_p 0.5 log sigma^2
    float AO[32];       // a_out per c
};

// One pass over n: recompute votes v[n,c,:] from fp16 weights with packed
// f32x2 FMA; optionally the E-step (warp softmax over c=lane, pass-constant
// shift M0) fused with the next M-step accumulation.
template <bool HASE>
__device__ __forceinline__ void vote_pass(Smem& sm, int lane, int g, int tid) {
    u64 A2[8], B2[8];
    float Lr2 = 0.f, M0 = 0.f;
    if (HASE) {
        float C = 0.f;
#pragma unroll
        for (int p2 = 0; p2 < 8; p2++) {
            float m0_ = sm.MU[lane * 17 + 2 * p2], m1_ = sm.MU[lane * 17 + 2 * p2 + 1];
            float i0 = sm.I2S[lane * 17 + 2 * p2], i1 = sm.I2S[lane * 17 + 2 * p2 + 1];
            A2[p2] = pk2(i0, i1);
            B2[p2] = pk2(-2.0f * i0 * m0_, -2.0f * i1 * m1_);
            C = fmaf(i0 * m0_, m0_, C);
            C = fmaf(i1 * m1_, m1_, C);
        }
        Lr2 = sm.Lc[lane] - C;
        M0 = warp_max(Lr2);  // upper bound of ln over lanes (ds>=0): safe softmax shift
    }
    u64 T1[8], T2[8];
#pragma unroll
    for (int p2 = 0; p2 < 8; p2++) { T1[p2] = 0ull; T2[p2] = 0ull; }
    float rsum = 0.f;

    const uint4* whv = reinterpret_cast<const uint4*>(g_wh);  // 1 uint4 = 8 halves
    const ulonglong2* ps2base = reinterpret_cast<const ulonglong2*>(sm.pose2);

#pragma unroll 2
    for (int n = g; n < NCAP; n += 8) {
        // weight loads: 2×LDG.128 per thread; warp-contiguous 512B each (L1-resident)
        uint4 ua = __ldg(whv + (n * 2 + 0) * 32 + lane);  // rows j=0,1
        uint4 ub = __ldg(whv + (n * 2 + 1) * 32 + lane);  // rows j=2,3
        const __half2* ha = reinterpret_cast<const __half2*>(&ua);
        const __half2* hb = reinterpret_cast<const __half2*>(&ub);
        u64 w00 = h2f2(ha[0]), w01 = h2f2(ha[1]);  // row j=0, k-pairs (0,1),(2,3)
        u64 w10 = h2f2(ha[2]), w11 = h2f2(ha[3]);
        u64 w20 = h2f2(hb[0]), w21 = h2f2(hb[1]);
        u64 w30 = h2f2(hb[2]), w31 = h2f2(hb[3]);

        const ulonglong2* ps2 = ps2base + n * 8;  // 32 dup floats per n
        u64 v2[8];  // v pairs: v2[2i+h] = (v[4i+2h], v[4i+2h+1])
#pragma unroll
        for (int i = 0; i < 4; i++) {
            ulonglong2 pa = ps2[2 * i];      // (p0,p0),(p1,p1)
            ulonglong2 pb = ps2[2 * i + 1];  // (p2,p2),(p3,p3)
            v2[2 * i + 0] = fma2_(pa.x, w00, fma2_(pa.y, w10, fma2_(pb.x, w20, mul2_(pb.y, w30))));
            v2[2 * i + 1] = fma2_(pa.x, w01, fma2_(pa.y, w11, fma2_(pb.x, w21, mul2_(pb.y, w31))));
        }
        float rn;
        if (HASE) {
            // ln = Lr' - sum_p (A_p v_p + B_p) v_p   (packed)
            u64 ds2 = 0ull;
#pragma unroll
            for (int p2 = 0; p2 < 8; p2++) {
                u64 t = fma2_(A2[p2], v2[p2], B2[p2]);
                ds2 = fma2_(t, v2[p2], ds2);
            }
            float2 dsf = upk2(ds2);
            float ln = Lr2 - (dsf.x + dsf.y);
            float e = __expf(ln - M0);
            float se = warp_sum(e);
            if (se < 1e-37f) {  // warp-uniform rescue: exact max (never in practice)
                float m = warp_max(ln);
                e = __expf(ln - m);
                se = warp_sum(e);
            }
            rn = sm.a[n] * __fdividef(e, se);  // r = softmax_c * a_in
        } else {
            rn = sm.a[n] * (1.0f / 32.0f);  // iter-0: r0 = a_in / C
        }
        rsum += rn;
        u64 rn2 = pk2(rn, rn);
#pragma unroll
        for (int p2 = 0; p2 < 8; p2++) {
            u64 rv = mul2_(rn2, v2[p2]);
            T1[p2] = add2_(T1[p2], rv);
            T2[p2] = fma2_(rv, v2[p2], T2[p2]);
        }
    }

    // ---- cross-warp reduction (deterministic, conflict-free stride-17) ----
#pragma unroll
    for (int p2 = 0; p2 < 8; p2++) {
        float2 t = upk2(T1[p2]);
        sm.WS[g * 548 + lane * 17 + 2 * p2] = t.x;
        sm.WS[g * 548 + lane * 17 + 2 * p2 + 1] = t.y;
    }
    sm.RSB[g * 33 + lane] = rsum;
    __syncthreads();
    for (int q = tid; q < 512; q += 256) {
        int c = q >> 4, p = q & 15;
        float s = 0.f;
#pragma unroll
        for (int gg = 0; gg < 8; gg++) s += sm.WS[gg * 548 + c * 17 + p];
        sm.S1[c * 17 + p] = s;
    }
    if (tid < 32) {
        float s = 0.f;
#pragma unroll
        for (int gg = 0; gg < 8; gg++) s += sm.RSB[gg * 33 + tid];
        sm.RS[tid] = s;
    }
    __syncthreads();
#pragma unroll
    for (int p2 = 0; p2 < 8; p2++) {
        float2 t = upk2(T2[p2]);
        sm.WS[g * 548 + lane * 17 + 2 * p2] = t.x;
        sm.WS[g * 548 + lane * 17 + 2 * p2 + 1] = t.y;
    }
    __syncthreads();
    for (int q = tid; q < 512; q += 256) {
        int c = q >> 4, p = q & 15;
        float s = 0.f;
#pragma unroll
        for (int gg = 0; gg < 8; gg++) s += sm.WS[gg * 548 + c * 17 + p];
        sm.S2[c * 17 + p] = s;
    }
    __syncthreads();
}

// M-step statistics: mu, sigma^2 (E[v^2]-mu^2 with exact coeff normalization),
// a_out, and the per-c softmax constant Lc.
__device__ __forceinline__ void stats(Smem& sm, const float* __restrict__ bu,
                                      const float* __restrict__ ba, int tid) {
    for (int q = tid; q < 512; q += 256) {
        int c = q >> 4, p = q & 15, qi = c * 17 + p;
        float rs = sm.RS[c];
        float inv = __fdividef(1.0f, rs + EPSF);
        float mu = sm.S1[qi] * inv;
        // sigma^2 = S2/(rs+eps) - mu^2 * (2 - rs/(rs+eps)) + eps
        float sig = fmaf(-mu * mu, 2.0f - rs * inv, sm.S2[qi] * inv) + EPSF;
        sm.MU[qi] = mu;
        sm.I2S[qi] = __fdividef(0.5f, sig);
        sm.WS[qi] = 0.5f * __logf(sig);  // halflog buffer (WS reuse)
    }
    __syncthreads();
    if (tid < 32) {
        int c = tid;
        float sumh = 0.f;
#pragma unroll
        for (int p = 0; p < 16; p++) sumh += sm.WS[c * 17 + p];
        float cost = (16.0f * bu[c] + sumh) * sm.RS[c];
        float logit = LAMBDAF * (ba[c] - cost);
        float ao = __fdividef(1.0f, 1.0f + __expf(-logit));
        sm.AO[c] = ao;
        sm.Lc[c] = __logf(ao + EPSF) - sumh;
    }
    __syncthreads();
}

__global__ __launch_bounds__(256, 2) void convcaps_kernel(
    const float* __restrict__ x, const float* __restrict__ a,
    const float* __restrict__ bu, const float* __restrict__ ba,
    const int* __restrict__ itp, float* __restrict__ out) {
    __shared__ Smem sm;
    int tid = threadIdx.x, lane = tid & 31, g = tid >> 5;
    int pid = blockIdx.x;
    int b = pid / 196;
    int rem = pid - b * 196;
    int oy = rem / 14;
    int ox = rem - oy * 14;

    // Patch gather (float4-vectorized), written DUPLICATED for f32x2 operands:
    //   pose2[n*32 + p*2 + {0,1}] = x[b, oy+ki, ox+kj, bc, p]
    for (int q = tid; q < 576; q += 256) {
        int n = q >> 2, f = q & 3;
        int bc = n & 15, kk = n >> 4;
        int ki = kk / 3, kj = kk - ki * 3;
        const float4* src = reinterpret_cast<const float4*>(
            x + (((size_t)(b * 16 + oy + ki) * 16 + (ox + kj)) * 16 + bc) * 16);
        float4 t = __ldg(src + f);
        float4* dst = reinterpret_cast<float4*>(sm.pose2 + n * 32 + f * 8);
        dst[0] = make_float4(t.x, t.x, t.y, t.y);
        dst[1] = make_float4(t.z, t.z, t.w, t.w);
    }
    for (int n = tid; n < NCAP; n += 256) {
        int bc = n & 15, kk = n >> 4;
        int ki = kk / 3, kj = kk - ki * 3;
        sm.a[n] = a[((size_t)(b * 16 + oy + ki) * 16 + (ox + kj)) * 16 + bc];
    }
    __syncthreads();

    int iters = 2;
    if (itp) {
        int iv = __ldg(itp);
        if (iv >= 1 && iv <= 64) {
            iters = iv;
        } else {
            float f = __int_as_float(iv);  // guard against float-encoded scalar
            if (f >= 1.0f && f <= 64.0f) iters = (int)f;
        }
    }

    // iteration 0: uniform responsibilities
    vote_pass<false>(sm, lane, g, tid);
    stats(sm, bu, ba, tid);
    // iterations 1..iters-1: fused E-step (of prev iter) + M-accumulation
    for (int it = 1; it < iters; ++it) {
        vote_pass<true>(sm, lane, g, tid);
        stats(sm, bu, ba, tid);
    }

    // outputs: p_out (pid*512 + c*16+p) then a_out (POUT_ELEMS + pid*32 + c)
    float* pout = out + (size_t)pid * 512;
    for (int q = tid; q < 512; q += 256) {
        int c = q >> 4, p = q & 15;
        pout[q] = sm.MU[c * 17 + p];
    }
    if (tid < 32) out[POUT_ELEMS + pid * 32 + tid] = sm.AO[tid];
}

extern "C" void kernel_launch(void* const* d_in, const int* in_sizes, int n_in,
                              void* d_out, int out_size) {
    const float* x = (const float*)d_in[0];
    const float* a = (const float*)d_in[1];
    const float* w = (const float*)d_in[2];
    const float* bu = (const float*)d_in[3];
    const float* ba = (const float*)d_in[4];
    const int* itp = (n_in >= 6) ? (const int*)d_in[5] : nullptr;
    convert_w_kernel<<<(WHALF_ELEMS / 8 + 255) / 256, 256>>>(w);
    convcaps_kernel<<<NPOS, 256>>>(x, a, bu, ba, itp, (float*)d_out);
}

// round 7
// speedup vs baseline: 1.0888x; 1.0888x over previous
#include <cuda_runtime.h>
#include <cuda_fp16.h>
#include <cstddef>

#define EPSF 1e-6f
#define LAMBDAF 0.01f

// Problem constants (fixed shapes)
//  x: (4,16,16,16,16)  a: (4,16,16,16,1)  w: (144,32,4,4)
//  out: p_out (4,14,14,32,16) ++ a_out (4,14,14,32,1)
#define NCAP 144
#define CCAP 32
#define NPOS 784           // 4*14*14
#define POUT_ELEMS 401408  // 784*32*16
#define WHALF_ELEMS (NCAP * CCAP * 16)  // 73728 halves = 144KB (L1-resident)

// fp16 weight staging buffer, layout [n][k2][c][8]:
//   wh[((n*2+k2)*32 + c)*8 + j] = w[n][c][ k2*8 + j ]
__device__ __half g_wh[WHALF_ELEMS];

// One thread produces one uint4 (8 halves) from two float4 loads.
__global__ void convert_w_kernel(const float* __restrict__ w) {
    int q = blockIdx.x * 256 + threadIdx.x;  // 0..9215
    if (q >= WHALF_ELEMS / 8) return;
    int c = q & 31;
    int k2 = (q >> 5) & 1;
    int n = q >> 6;
    const float4* src = reinterpret_cast<const float4*>(w + ((n * 32 + c) << 4) + k2 * 8);
    float4 f0 = __ldg(src + 0), f1 = __ldg(src + 1);
    __half2 h[4];
    h[0] = __floats2half2_rn(f0.x, f0.y);
    h[1] = __floats2half2_rn(f0.z, f0.w);
    h[2] = __floats2half2_rn(f1.x, f1.y);
    h[3] = __floats2half2_rn(f1.z, f1.w);
    reinterpret_cast<uint4*>(g_wh)[q] = *reinterpret_cast<uint4*>(h);
}

__device__ __forceinline__ float warp_max(float v) {
#pragma unroll
    for (int o = 16; o; o >>= 1) v = fmaxf(v, __shfl_xor_sync(0xffffffffu, v, o));
    return v;
}
__device__ __forceinline__ float warp_sum(float v) {
#pragma unroll
    for (int o = 16; o; o >>= 1) v += __shfl_xor_sync(0xffffffffu, v, o);
    return v;
}

struct Smem {
    float pose[2304];   // [n*16 + p], pose patch
    float a[144];       // a_in per n
    float WS[8 * 548];  // per-warp reduction staging (stride-17 padded)
    float M1[544];      // S1 (sum r*v) then mu, in place  [c*17+p]
    float M2[544];      // I2S = 1/(2 sigma^2)             [c*17+p]
    float RSB[8 * 33];  // per-warp rsum staging
    float RS[32];       // r_sum per c
    float SH[32];       // sum_p 0.5*log(sigma^2) per c
    float Lc[32];       // log(a_out+eps) - SH[c]
    float AO[32];       // a_out per c
};

// Compute 16 votes for capsule n (weights fp16, L1-resident; pose smem bcast).
__device__ __forceinline__ void votes16(const Smem& sm, int n, int lane, float* v) {
    const uint4* whv = reinterpret_cast<const uint4*>(g_wh);
    uint4 ua = __ldg(whv + (n * 2 + 0) * 32 + lane);  // rows j=0,1
    uint4 ub = __ldg(whv + (n * 2 + 1) * 32 + lane);  // rows j=2,3
    const __half2* ha = reinterpret_cast<const __half2*>(&ua);
    const __half2* hb = reinterpret_cast<const __half2*>(&ub);
    float w0[4], w1[4], w2[4], w3[4];
    float2 t;
    t = __half22float2(ha[0]); w0[0] = t.x; w0[1] = t.y;
    t = __half22float2(ha[1]); w0[2] = t.x; w0[3] = t.y;
    t = __half22float2(ha[2]); w1[0] = t.x; w1[1] = t.y;
    t = __half22float2(ha[3]); w1[2] = t.x; w1[3] = t.y;
    t = __half22float2(hb[0]); w2[0] = t.x; w2[1] = t.y;
    t = __half22float2(hb[1]); w2[2] = t.x; w2[3] = t.y;
    t = __half22float2(hb[2]); w3[0] = t.x; w3[1] = t.y;
    t = __half22float2(hb[3]); w3[2] = t.x; w3[3] = t.y;
    const float* ps = sm.pose + n * 16;
#pragma unroll
    for (int i = 0; i < 4; i++) {
        float p0 = ps[4 * i + 0], p1 = ps[4 * i + 1], p2 = ps[4 * i + 2], p3 = ps[4 * i + 3];
#pragma unroll
        for (int k = 0; k < 4; k++)
            v[4 * i + k] = fmaf(p0, w0[k], fmaf(p1, w1[k], fmaf(p2, w2[k], p3 * w3[k])));
    }
}

// Shared epilogue of a vote pass: stage + reduce T1/rsum into M1/RS, stage T2.
// (T2's reduction is merged into stats() to save one barrier.)
__device__ __forceinline__ void pass_reduce(Smem& sm, const float* T1, const float* T2,
                                            float rsum, int lane, int g, int tid) {
#pragma unroll
    for (int p = 0; p < 16; p++) sm.WS[g * 548 + lane * 17 + p] = T1[p];
    sm.RSB[g * 33 + lane] = rsum;
    __syncthreads();
    for (int q = tid; q < 512; q += 256) {
        int c = q >> 4, p = q & 15;
        float s = 0.f;
#pragma unroll
        for (int gg = 0; gg < 8; gg++) s += sm.WS[gg * 548 + c * 17 + p];
        sm.M1[c * 17 + p] = s;
    }
    if (tid < 32) {
        float s = 0.f;
#pragma unroll
        for (int gg = 0; gg < 8; gg++) s += sm.RSB[gg * 33 + tid];
        sm.RS[tid] = s;
    }
    __syncthreads();
#pragma unroll
    for (int p = 0; p < 16; p++) sm.WS[g * 548 + lane * 17 + p] = T2[p];
    __syncthreads();
}

// Pass 0: uniform responsibilities r0 = a_n / C.
__device__ __forceinline__ void vote_pass0(Smem& sm, int lane, int g, int tid) {
    float T1[16], T2[16];
#pragma unroll
    for (int p = 0; p < 16; p++) { T1[p] = 0.f; T2[p] = 0.f; }
    float rsum = 0.f;
#pragma unroll 2
    for (int n = g; n < NCAP; n += 8) {
        float v[16];
        votes16(sm, n, lane, v);
        float rn = sm.a[n] * (1.0f / 32.0f);
        rsum += rn;
#pragma unroll
        for (int p = 0; p < 16; p++) {
            float rv = rn * v[p];
            T1[p] += rv;
            T2[p] = fmaf(rv, v[p], T2[p]);
        }
    }
    pass_reduce(sm, T1, T2, rsum, lane, g, tid);
}

// E+M pass: fused E-step (warp softmax over c=lane, pass-constant shift folded
// into Lr) + next M accumulation. Two capsules (n, n+8) per loop iteration with
// the two shuffle-reduction chains interleaved to halve exposed SHFL latency.
__device__ __forceinline__ void vote_passE(Smem& sm, int lane, int g, int tid) {
    float A[16], Bv[16];
    float C = 0.f;
#pragma unroll
    for (int p = 0; p < 16; p++) {
        float m_ = sm.M1[lane * 17 + p];
        float ii = sm.M2[lane * 17 + p];
        A[p] = ii;
        Bv[p] = -2.0f * ii * m_;
        C = fmaf(ii * m_, m_, C);
    }
    float Lr2 = sm.Lc[lane] - C;
    float Lrm = Lr2 - warp_max(Lr2);  // shift folded in: ln' = Lrm - ds  (<= 0)

    float T1[16], T2[16];
#pragma unroll
    for (int p = 0; p < 16; p++) { T1[p] = 0.f; T2[p] = 0.f; }
    float rsum = 0.f;

#pragma unroll 1
    for (int n = g; n < NCAP; n += 16) {  // 9 iterations, pair (n, n+8)
        float vA[16], vB[16];
        votes16(sm, n, lane, vA);
        float dsA = 0.f;
#pragma unroll
        for (int p = 0; p < 16; p++) {
            float t = fmaf(A[p], vA[p], Bv[p]);
            dsA = fmaf(t, vA[p], dsA);
        }
        float eA = __expf(Lrm - dsA);
        votes16(sm, n + 8, lane, vB);
        float dsB = 0.f;
#pragma unroll
        for (int p = 0; p < 16; p++) {
            float t = fmaf(A[p], vB[p], Bv[p]);
            dsB = fmaf(t, vB[p], dsB);
        }
        float eB = __expf(Lrm - dsB);
        // interleaved butterfly sums over the 32 lanes (softmax over c)
        float seA = eA, seB = eB;
#pragma unroll
        for (int o = 16; o; o >>= 1) {
            seA += __shfl_xor_sync(0xffffffffu, seA, o);
            seB += __shfl_xor_sync(0xffffffffu, seB, o);
        }
        if (seA < 1e-37f || seB < 1e-37f) {  // warp-uniform rescue (never in practice)
            float mA = warp_max(Lrm - dsA);
            eA = __expf(Lrm - dsA - mA);
            seA = warp_sum(eA);
            float mB = warp_max(Lrm - dsB);
            eB = __expf(Lrm - dsB - mB);
            seB = warp_sum(eB);
        }
        float rnA = sm.a[n] * __fdividef(eA, seA);
        float rnB = sm.a[n + 8] * __fdividef(eB, seB);
        rsum += rnA + rnB;
#pragma unroll
        for (int p = 0; p < 16; p++) {
            float rvA = rnA * vA[p];
            float rvB = rnB * vB[p];
            T1[p] += rvA + rvB;
            T2[p] = fmaf(rvA, vA[p], fmaf(rvB, vB[p], T2[p]));
        }
    }
    pass_reduce(sm, T1, T2, rsum, lane, g, tid);
}

// M-step statistics. Phase 1 also finishes the T2 reduction (staged in WS) and
// computes sum_p 0.5*log(sigma^2) per c via 16-lane shuffles (no smem round-trip).
__device__ __forceinline__ void stats(Smem& sm, const float* __restrict__ bu,
                                      const float* __restrict__ ba, int tid) {
    for (int q = tid; q < 512; q += 256) {
        int c = q >> 4, p = q & 15, qi = c * 17 + p;
        float s2 = 0.f;
#pragma unroll
        for (int gg = 0; gg < 8; gg++) s2 += sm.WS[gg * 548 + c * 17 + p];
        float rs = sm.RS[c];
        float inv = __fdividef(1.0f, rs + EPSF);
        float mu = sm.M1[qi] * inv;
        // sigma^2 = S2/(rs+eps) - mu^2 * (2 - rs/(rs+eps)) + eps
        float sig = fmaf(-mu * mu, 2.0f - rs * inv, s2 * inv) + EPSF;
        sm.M1[qi] = mu;  // in place: S1 -> mu
        sm.M2[qi] = __fdividef(0.5f, sig);
        // sum of 0.5*log(sig) over the 16 lanes sharing this c (lane = c*16+p mod 32)
        float hl = 0.5f * __logf(sig);
#pragma unroll
        for (int o = 1; o < 16; o <<= 1) hl += __shfl_xor_sync(0xffffffffu, hl, o);
        if (p == 0) sm.SH[c] = hl;
    }
    __syncthreads();
    if (tid < 32) {
        int c = tid;
        float sumh = sm.SH[c];
        float cost = (16.0f * bu[c] + sumh) * sm.RS[c];
        float logit = LAMBDAF * (ba[c] - cost);
        float ao = __fdividef(1.0f, 1.0f + __expf(-logit));
        sm.AO[c] = ao;
        sm.Lc[c] = __logf(ao + EPSF) - sumh;
    }
    __syncthreads();
}

__global__ __launch_bounds__(256, 2) void convcaps_kernel(
    const float* __restrict__ x, const float* __restrict__ a,
    const float* __restrict__ bu, const float* __restrict__ ba,
    const int* __restrict__ itp, float* __restrict__ out) {
    __shared__ Smem sm;
    int tid = threadIdx.x, lane = tid & 31, g = tid >> 5;
    int pid = blockIdx.x;
    int b = pid / 196;
    int rem = pid - b * 196;
    int oy = rem / 14;
    int ox = rem - oy * 14;

    // Patch gather (float4-vectorized): n = (ki*3+kj)*16 + bc
    for (int q = tid; q < 576; q += 256) {
        int n = q >> 2, f = q & 3;
        int bc = n & 15, kk = n >> 4;
        int ki = kk / 3, kj = kk - ki * 3;
        const float4* src = reinterpret_cast<const float4*>(
            x + (((size_t)(b * 16 + oy + ki) * 16 + (ox + kj)) * 16 + bc) * 16);
        reinterpret_cast<float4*>(sm.pose)[q] = __ldg(src + f);
    }
    for (int n = tid; n < NCAP; n += 256) {
        int bc = n & 15, kk = n >> 4;
        int ki = kk / 3, kj = kk - ki * 3;
        sm.a[n] = a[((size_t)(b * 16 + oy + ki) * 16 + (ox + kj)) * 16 + bc];
    }
    __syncthreads();

    int iters = 2;
    if (itp) {
        int iv = __ldg(itp);
        if (iv >= 1 && iv <= 64) {
            iters = iv;
        } else {
            float f = __int_as_float(iv);  // guard against float-encoded scalar
            if (f >= 1.0f && f <= 64.0f) iters = (int)f;
        }
    }

    // iteration 0: uniform responsibilities
    vote_pass0(sm, lane, g, tid);
    stats(sm, bu, ba, tid);
    // iterations 1..iters-1: fused E-step (of prev iter) + M-accumulation
    for (int it = 1; it < iters; ++it) {
        vote_passE(sm, lane, g, tid);
        stats(sm, bu, ba, tid);
    }

    // outputs: p_out (pid*512 + c*16+p) then a_out (POUT_ELEMS + pid*32 + c)
    float* pout = out + (size_t)pid * 512;
    for (int q = tid; q < 512; q += 256) {
        int c = q >> 4, p = q & 15;
        pout[q] = sm.M1[c * 17 + p];
    }
    if (tid < 32) out[POUT_ELEMS + pid * 32 + tid] = sm.AO[tid];
}

extern "C" void kernel_launch(void* const* d_in, const int* in_sizes, int n_in,
                              void* d_out, int out_size) {
    const float* x = (const float*)d_in[0];
    const float* a = (const float*)d_in[1];
    const float* w = (const float*)d_in[2];
    const float* bu = (const float*)d_in[3];
    const float* ba = (const float*)d_in[4];
    const int* itp = (n_in >= 6) ? (const int*)d_in[5] : nullptr;
    convert_w_kernel<<<(WHALF_ELEMS / 8 + 255) / 256, 256>>>(w);
    convcaps_kernel<<<NPOS, 256>>>(x, a, bu, ba, itp, (float*)d_out);
}